// round 3
// baseline (speedup 1.0000x reference)
#include <cuda_runtime.h>

// out[b,i,h,w] = sum_j x[b,j,h,w] - x[b,i,h,w]
// x: fp32 [16, 256, 128, 128]
//
// Single-read / single-write, register-resident channel values.
// R3: shrink payload to 8 channels x float2 (16 regs) so THREE 512-thread
// blocks co-reside per SM (launch_bounds(512,3), target <=42 regs). More
// co-resident blocks = finer mixing of load-phase and store-phase warps at
// HBM (R1: 1 blk/SM -> 66% DRAM; R2: 2 blk/SM -> 77%).

constexpr int B_DIM  = 16;
constexpr int C_DIM  = 256;
constexpr int S_DIM  = 128 * 128;        // spatial per (b,c)
constexpr int GROUPS = 32;               // channel groups per block
constexpr int CPT    = C_DIM / GROUPS;   // 8 channels per thread
constexpr int LANES  = 16;               // float2 lanes per group
constexpr int VEC    = 2;                // floats per lane (float2)
constexpr int SPB    = LANES * VEC;      // 32 spatial positions per block
constexpr int THREADS = GROUPS * LANES;  // 512

__global__ __launch_bounds__(THREADS, 3)
void neighbour_channels_kernel(const float* __restrict__ x,
                               float* __restrict__ out)
{
    __shared__ float2 red[GROUPS][LANES];

    const int lane = threadIdx.x & (LANES - 1);
    const int grp  = threadIdx.x >> 4;           // 0..31

    const int tiles_per_b = S_DIM / SPB;         // 512
    const int tile = blockIdx.x % tiles_per_b;
    const int b    = blockIdx.x / tiles_per_b;

    const long long spatial = (long long)tile * SPB + lane * VEC;
    const long long base    = (long long)b * C_DIM * S_DIM
                            + (long long)grp * CPT * S_DIM
                            + spatial;

    const float2* __restrict__ xp = (const float2*)(x + base);

    // Load CPT channels (float2 each) into registers.
    float2 v[CPT];
#pragma unroll
    for (int i = 0; i < CPT; ++i) {
        v[i] = xp[(long long)i * (S_DIM / 2)];
    }

    float2 sum = make_float2(0.0f, 0.0f);
#pragma unroll
    for (int i = 0; i < CPT; ++i) {
        sum.x += v[i].x;
        sum.y += v[i].y;
    }

    // Cross-group reduction: 32 partials per lane (conflict-free LDS.64,
    // 2-way broadcast within each warp half).
    red[grp][lane] = sum;
    __syncthreads();

    float2 total = make_float2(0.0f, 0.0f);
#pragma unroll
    for (int g = 0; g < GROUPS; ++g) {
        float2 p = red[g][lane];
        total.x += p.x;
        total.y += p.y;
    }

    // Write out = total - x from registers (no second global read).
    float2* __restrict__ op = (float2*)(out + base);
#pragma unroll
    for (int i = 0; i < CPT; ++i) {
        float2 o;
        o.x = total.x - v[i].x;
        o.y = total.y - v[i].y;
        op[(long long)i * (S_DIM / 2)] = o;
    }
}

extern "C" void kernel_launch(void* const* d_in, const int* in_sizes, int n_in,
                              void* d_out, int out_size)
{
    const float* x = (const float*)d_in[0];
    float* out = (float*)d_out;

    const int grid = B_DIM * (S_DIM / SPB);  // 16 * 512 = 8192 blocks
    neighbour_channels_kernel<<<grid, THREADS>>>(x, out);
}

// round 4
// speedup vs baseline: 1.1195x; 1.1195x over previous
#include <cuda_runtime.h>

// out[b,i,h,w] = sum_j x[b,j,h,w] - x[b,i,h,w]
// x: fp32 [16, 256, 128, 128]
//
// Single-read / single-write, register-resident channel values.
// R4: float4 payload. 256-thread blocks, CPT=8 channels x float4 = 32 payload
// regs -> 4 blocks/SM (1024 threads). Bytes-in-flight per SM restored to
// R2's 131 KB (R3's regression traced to MLP drop: 98 KB in flight), with
// 4 independently-barriered blocks for finer load/store phase interleaving
// and half the LDG/STG instruction count of R2.

constexpr int B_DIM  = 16;
constexpr int C_DIM  = 256;
constexpr int S_DIM  = 128 * 128;        // spatial per (b,c)
constexpr int GROUPS = 32;               // channel groups per block
constexpr int CPT    = C_DIM / GROUPS;   // 8 channels per thread
constexpr int LANES  = 8;                // float4 lanes per group
constexpr int VEC    = 4;                // floats per lane (float4)
constexpr int SPB    = LANES * VEC;      // 32 spatial positions per block
constexpr int THREADS = GROUPS * LANES;  // 256

__global__ __launch_bounds__(THREADS, 4)
void neighbour_channels_kernel(const float* __restrict__ x,
                               float* __restrict__ out)
{
    __shared__ float4 red[GROUPS][LANES];

    const int lane = threadIdx.x & (LANES - 1);
    const int grp  = threadIdx.x >> 3;           // 0..31

    const int tiles_per_b = S_DIM / SPB;         // 512
    const int tile = blockIdx.x % tiles_per_b;
    const int b    = blockIdx.x / tiles_per_b;

    const long long spatial = (long long)tile * SPB + lane * VEC;
    const long long base    = (long long)b * C_DIM * S_DIM
                            + (long long)grp * CPT * S_DIM
                            + spatial;

    const float4* __restrict__ xp = (const float4*)(x + base);

    // Load CPT channels (float4 each) into registers; channel stride in
    // float4 units is S_DIM/4.
    float4 v[CPT];
#pragma unroll
    for (int i = 0; i < CPT; ++i) {
        v[i] = xp[(long long)i * (S_DIM / 4)];
    }

    float4 sum = make_float4(0.0f, 0.0f, 0.0f, 0.0f);
#pragma unroll
    for (int i = 0; i < CPT; ++i) {
        sum.x += v[i].x;
        sum.y += v[i].y;
        sum.z += v[i].z;
        sum.w += v[i].w;
    }

    // Cross-group reduction: 32 partials per lane.
    red[grp][lane] = sum;
    __syncthreads();

    float4 total = make_float4(0.0f, 0.0f, 0.0f, 0.0f);
#pragma unroll
    for (int g = 0; g < GROUPS; ++g) {
        float4 p = red[g][lane];
        total.x += p.x;
        total.y += p.y;
        total.z += p.z;
        total.w += p.w;
    }

    // Write out = total - x from registers (no second global read).
    float4* __restrict__ op = (float4*)(out + base);
#pragma unroll
    for (int i = 0; i < CPT; ++i) {
        float4 o;
        o.x = total.x - v[i].x;
        o.y = total.y - v[i].y;
        o.z = total.z - v[i].z;
        o.w = total.w - v[i].w;
        op[(long long)i * (S_DIM / 4)] = o;
    }
}

extern "C" void kernel_launch(void* const* d_in, const int* in_sizes, int n_in,
                              void* d_out, int out_size)
{
    const float* x = (const float*)d_in[0];
    float* out = (float*)d_out;

    const int grid = B_DIM * (S_DIM / SPB);  // 16 * 512 = 8192 blocks
    neighbour_channels_kernel<<<grid, THREADS>>>(x, out);
}